// round 3
// baseline (speedup 1.0000x reference)
#include <cuda_runtime.h>
#include <math.h>

#define NN 50000
#define EE 800000
#define DD 96
#define HIDN 128
#define OUTN 8
#define NBS 196   // scan blocks = ceil(NN/256)

typedef unsigned long long ull;

// ------------------------- device scratch (no allocs allowed) ----------------
__device__ float g_h[(size_t)NN * DD];
__device__ float g_hnew[(size_t)NN * DD];
__device__ float g_ABDE[(size_t)4 * NN * DD];   // A,B,D,E
__device__ float g_e[(size_t)EE * DD];          // permuted (CSR dst order)
__device__ float g_enew[(size_t)EE * DD];       // permuted
__device__ int   g_cnt[NN];
__device__ int   g_ptr[NN + 1];
__device__ int   g_woff[NN];
__device__ int   g_eid[EE];
__device__ int   g_srcp[EE];
__device__ int   g_dstp[EE];
__device__ int   g_bsum[256];
__device__ int   g_boff[256];
__device__ double g_esum[DD], g_esq[DD], g_hsum[DD], g_hsq[DD];
__device__ float g_escale[DD], g_eshift[DD], g_hscale[DD], g_hshift[DD];

// ------------------------- packed f32x2 helpers ------------------------------
__device__ __forceinline__ ull pk2(float lo, float hi) {
    ull r; asm("mov.b64 %0,{%1,%2};" : "=l"(r) : "f"(lo), "f"(hi)); return r;
}
__device__ __forceinline__ ull fma2(ull a, ull b, ull c) {
    ull d; asm("fma.rn.f32x2 %0,%1,%2,%3;" : "=l"(d) : "l"(a), "l"(b), "l"(c)); return d;
}
__device__ __forceinline__ float2 upk(ull v) {
    float2 f; asm("mov.b64 {%0,%1},%2;" : "=f"(f.x), "=f"(f.y) : "l"(v)); return f;
}

// ------------------------- setup kernels -------------------------------------
__global__ void k_zero() {
    int i = blockIdx.x * blockDim.x + threadIdx.x;
    if (i < NN) g_cnt[i] = 0;
    if (i < DD) { g_esum[i] = 0.0; g_esq[i] = 0.0; g_hsum[i] = 0.0; g_hsq[i] = 0.0; }
}

__global__ void k_embed_h(const float* __restrict__ h1, const float* __restrict__ h2,
                          const float* __restrict__ z,
                          const float* __restrict__ W, const float* __restrict__ b) {
    __shared__ float Ws[26 * DD];
    int t = threadIdx.x;
    for (int i = t; i < 26 * DD; i += blockDim.x) Ws[i] = W[i];
    __syncthreads();
    int idx = blockIdx.x * blockDim.x + t;
    if (idx >= NN * DD) return;
    int r = idx / DD, c = idx - (idx / DD) * DD;
    float acc = b[c];
#pragma unroll
    for (int k = 0; k < 6; k++)  acc += h1[r * 6 + k]  * Ws[k * DD + c];
#pragma unroll
    for (int k = 0; k < 4; k++)  acc += h2[r * 4 + k]  * Ws[(6 + k) * DD + c];
#pragma unroll
    for (int k = 0; k < 16; k++) acc += z[r * 16 + k]  * Ws[(10 + k) * DD + c];
    g_h[idx] = acc;
}

// ------------------------- CSR build (deterministic, parallel scan) -----------
__global__ void k_count(const int* __restrict__ dst) {
    int i = blockIdx.x * blockDim.x + threadIdx.x;
    if (i < EE) atomicAdd(&g_cnt[dst[i]], 1);
}

__global__ void k_scan1() {
    __shared__ int sh[256];
    int t = threadIdx.x, b = blockIdx.x;
    int j = b * 256 + t;
    int v = (j < NN) ? g_cnt[j] : 0;
    sh[t] = v; __syncthreads();
    for (int off = 1; off < 256; off <<= 1) {
        int u = (t >= off) ? sh[t - off] : 0;
        __syncthreads();
        sh[t] += u;
        __syncthreads();
    }
    if (j < NN) g_ptr[j] = sh[t] - v;
    if (t == 255) g_bsum[b] = sh[t];
}

__global__ void k_scan2() {
    __shared__ int sh[256];
    int t = threadIdx.x;
    int v = (t < NBS) ? g_bsum[t] : 0;
    sh[t] = v; __syncthreads();
    for (int off = 1; off < 256; off <<= 1) {
        int u = (t >= off) ? sh[t - off] : 0;
        __syncthreads();
        sh[t] += u;
        __syncthreads();
    }
    g_boff[t] = sh[t] - v;
}

__global__ void k_scan3() {
    int j = blockIdx.x * blockDim.x + threadIdx.x;
    if (j < NN) {
        int p = g_ptr[j] + g_boff[j >> 8];
        g_ptr[j] = p; g_woff[j] = p;
    }
    if (j == 0) g_ptr[NN] = EE;
}

__global__ void k_fill(const int* __restrict__ dst) {
    int i = blockIdx.x * blockDim.x + threadIdx.x;
    if (i < EE) {
        int pos = atomicAdd(&g_woff[dst[i]], 1);
        g_eid[pos] = i;
    }
}

__global__ void k_sortseg() {
    int v = blockIdx.x * blockDim.x + threadIdx.x;
    if (v >= NN) return;
    int lo = g_ptr[v], hi = g_ptr[v + 1];
    for (int i = lo + 1; i < hi; i++) {
        int key = g_eid[i]; int j = i - 1;
        while (j >= lo && g_eid[j] > key) { g_eid[j + 1] = g_eid[j]; j--; }
        g_eid[j + 1] = key;
    }
}

// Embed edges directly into permuted (CSR) order; also build permuted src/dst.
__global__ __launch_bounds__(256) void k_embed_e_perm(const float* __restrict__ ef,
                                                      const int* __restrict__ src,
                                                      const int* __restrict__ dst,
                                                      const float* __restrict__ W,
                                                      const float* __restrict__ b) {
    __shared__ float Ws[4 * DD], bs[DD];
    int t = threadIdx.x;
    for (int i = t; i < 4 * DD; i += 256) Ws[i] = W[i];
    if (t < DD) bs[t] = b[t];
    __syncthreads();
    int w = t >> 5, ln = t & 31;
    int p = blockIdx.x * 8 + w;        // grid = EE/8 exact
    int ei = g_eid[p];
    float4 f = *(const float4*)(ef + (size_t)ei * 4);
    if (ln == 0) g_srcp[p] = src[ei];
    if (ln == 1) g_dstp[p] = dst[ei];
#pragma unroll
    for (int j = 0; j < 3; j++) {
        int c = ln + j * 32;
        g_e[(size_t)p * DD + c] = bs[c] + f.x * Ws[c] + f.y * Ws[DD + c]
                                 + f.z * Ws[2 * DD + c] + f.w * Ws[3 * DD + c];
    }
}

// ------------------------- fused node GEMM: [A|B|D|E] = h @ Wcat + bcat -------
// 64 rows/block, 8x8 per-thread tile, 384 threads.
// Lazily applies h += relu(bn(hnew)) from the previous layer (writes g_h).
__global__ __launch_bounds__(384) void k_matABDE(const float* __restrict__ WA_,
                                                 const float* __restrict__ WB_,
                                                 const float* __restrict__ WD_,
                                                 const float* __restrict__ WE_,
                                                 const float* __restrict__ bA_,
                                                 const float* __restrict__ bB_,
                                                 const float* __restrict__ bD_,
                                                 const float* __restrict__ bE_,
                                                 int apply) {
    extern __shared__ float dyn[];
    float* Ws = dyn;                    // [96][384] concat
    float* Xs = dyn + DD * 384;         // [64][96]
    float* Bs = Xs + 64 * DD;           // [384]
    int t = threadIdx.x;
    const float* wsrc[4] = {WA_, WB_, WD_, WE_};
    const float* bsrc[4] = {bA_, bB_, bD_, bE_};
#pragma unroll
    for (int m = 0; m < 4; m++) {
        for (int i = t; i < DD * DD; i += 384) {
            int k = i / DD, c = i - k * DD;
            Ws[k * 384 + m * DD + c] = wsrc[m][i];
        }
        if (t < DD) Bs[m * DD + t] = bsrc[m][t];
    }
    int row0 = blockIdx.x * 64;
    for (int i = t; i < 64 * 24; i += 384) {
        int r = i / 24, c4 = (i - (i / 24) * 24) * 4;
        int gr = row0 + r;
        float4 v = make_float4(0.f, 0.f, 0.f, 0.f);
        if (gr < NN) {
            size_t idx = (size_t)gr * DD + c4;
            v = *(const float4*)(g_h + idx);
            if (apply) {
                float4 en = *(const float4*)(g_hnew + idx);
                float4 sc = *(const float4*)(g_hscale + c4);
                float4 sh = *(const float4*)(g_hshift + c4);
                v.x += fmaxf(sc.x * en.x + sh.x, 0.f);
                v.y += fmaxf(sc.y * en.y + sh.y, 0.f);
                v.z += fmaxf(sc.z * en.z + sh.z, 0.f);
                v.w += fmaxf(sc.w * en.w + sh.w, 0.f);
                *(float4*)(g_h + idx) = v;
            }
        }
        *(float4*)(Xs + r * DD + c4) = v;
    }
    __syncthreads();
    int cg = t % 48, rg = t / 48;       // 48 col-groups x 8 row-groups
    int c0 = cg * 8, r0 = rg * 8;
    ull acc[8][4];
    ull bb[4];
#pragma unroll
    for (int j = 0; j < 4; j++) bb[j] = pk2(Bs[c0 + 2 * j], Bs[c0 + 2 * j + 1]);
#pragma unroll
    for (int r = 0; r < 8; r++)
#pragma unroll
        for (int j = 0; j < 4; j++) acc[r][j] = bb[j];
#pragma unroll 2
    for (int k = 0; k < DD; k += 2) {
        ulonglong2 w0a = *(const ulonglong2*)(Ws + k * 384 + c0);
        ulonglong2 w0b = *(const ulonglong2*)(Ws + k * 384 + c0 + 4);
        ulonglong2 w1a = *(const ulonglong2*)(Ws + (k + 1) * 384 + c0);
        ulonglong2 w1b = *(const ulonglong2*)(Ws + (k + 1) * 384 + c0 + 4);
#pragma unroll
        for (int r = 0; r < 8; r++) {
            float2 x = *(const float2*)(Xs + (r0 + r) * DD + k);
            ull x0 = pk2(x.x, x.x), x1 = pk2(x.y, x.y);
            acc[r][0] = fma2(x0, w0a.x, acc[r][0]);
            acc[r][1] = fma2(x0, w0a.y, acc[r][1]);
            acc[r][2] = fma2(x0, w0b.x, acc[r][2]);
            acc[r][3] = fma2(x0, w0b.y, acc[r][3]);
            acc[r][0] = fma2(x1, w1a.x, acc[r][0]);
            acc[r][1] = fma2(x1, w1a.y, acc[r][1]);
            acc[r][2] = fma2(x1, w1b.x, acc[r][2]);
            acc[r][3] = fma2(x1, w1b.y, acc[r][3]);
        }
    }
    int m = c0 / DD, cc = c0 - m * DD;   // 8 cols stay inside one matrix (96%8==0)
    float* outp = g_ABDE + (size_t)m * NN * DD;
#pragma unroll
    for (int r = 0; r < 8; r++) {
        int gr = row0 + r0 + r;
        if (gr < NN) {
            float2 a0 = upk(acc[r][0]), a1 = upk(acc[r][1]);
            float2 a2 = upk(acc[r][2]), a3 = upk(acc[r][3]);
            *(float4*)(outp + (size_t)gr * DD + cc)     = make_float4(a0.x, a0.y, a1.x, a1.y);
            *(float4*)(outp + (size_t)gr * DD + cc + 4) = make_float4(a2.x, a2.y, a3.x, a3.y);
        }
    }
}

// ------------------------- edge kernel (128 edges/block, 8x8 tiles) -----------
__global__ __launch_bounds__(192) void k_edge(const float* __restrict__ W,
                                              const float* __restrict__ b,
                                              int apply, int write_e, int do_stats) {
    extern __shared__ float dyn[];
    float* Ws = dyn;             // 96*96
    float* Es = dyn + DD * DD;   // 128*96
    __shared__ float s_sum[DD], s_sq[DD];
    __shared__ int s_src[128], s_dst[128];
    int t = threadIdx.x;
    if (t < DD) { s_sum[t] = 0.f; s_sq[t] = 0.f; }
    for (int i = t; i < DD * DD; i += 192) Ws[i] = W[i];
    int ebase = blockIdx.x * 128;   // EE % 128 == 0
    if (t < 128) { s_src[t] = g_srcp[ebase + t]; s_dst[t] = g_dstp[ebase + t]; }
    for (int i = t; i < 128 * 24; i += 192) {
        int r = i / 24, c4 = (i - (i / 24) * 24) * 4;
        size_t idx = (size_t)(ebase + r) * DD + c4;
        float4 v = *(const float4*)(g_e + idx);
        if (apply) {
            float4 en = *(const float4*)(g_enew + idx);
            float4 sc = *(const float4*)(g_escale + c4);
            float4 sh = *(const float4*)(g_eshift + c4);
            v.x += fmaxf(sc.x * en.x + sh.x, 0.f);
            v.y += fmaxf(sc.y * en.y + sh.y, 0.f);
            v.z += fmaxf(sc.z * en.z + sh.z, 0.f);
            v.w += fmaxf(sc.w * en.w + sh.w, 0.f);
            if (write_e) *(float4*)(g_e + idx) = v;
        }
        *(float4*)(Es + r * DD + c4) = v;
    }
    __syncthreads();
    int cg = t % 12, rg = t / 12;    // 12 col-groups x 16 row-groups
    int c0 = cg * 8, r0 = rg * 8;
    ull acc[8][4];
    ull bb[4];
#pragma unroll
    for (int j = 0; j < 4; j++) bb[j] = pk2(b[c0 + 2 * j], b[c0 + 2 * j + 1]);
#pragma unroll
    for (int r = 0; r < 8; r++)
#pragma unroll
        for (int j = 0; j < 4; j++) acc[r][j] = bb[j];
#pragma unroll 2
    for (int k = 0; k < DD; k += 2) {
        ulonglong2 w0a = *(const ulonglong2*)(Ws + k * DD + c0);
        ulonglong2 w0b = *(const ulonglong2*)(Ws + k * DD + c0 + 4);
        ulonglong2 w1a = *(const ulonglong2*)(Ws + (k + 1) * DD + c0);
        ulonglong2 w1b = *(const ulonglong2*)(Ws + (k + 1) * DD + c0 + 4);
#pragma unroll
        for (int r = 0; r < 8; r++) {
            float2 x = *(const float2*)(Es + (r0 + r) * DD + k);
            ull x0 = pk2(x.x, x.x), x1 = pk2(x.y, x.y);
            acc[r][0] = fma2(x0, w0a.x, acc[r][0]);
            acc[r][1] = fma2(x0, w0a.y, acc[r][1]);
            acc[r][2] = fma2(x0, w0b.x, acc[r][2]);
            acc[r][3] = fma2(x0, w0b.y, acc[r][3]);
            acc[r][0] = fma2(x1, w1a.x, acc[r][0]);
            acc[r][1] = fma2(x1, w1a.y, acc[r][1]);
            acc[r][2] = fma2(x1, w1b.x, acc[r][2]);
            acc[r][3] = fma2(x1, w1b.y, acc[r][3]);
        }
    }
    const float* Dh = g_ABDE + (size_t)2 * NN * DD;
    const float* Eh = g_ABDE + (size_t)3 * NN * DD;
    float cs[8] = {0,0,0,0,0,0,0,0}, cq[8] = {0,0,0,0,0,0,0,0};
#pragma unroll
    for (int r = 0; r < 8; r++) {
        int er = r0 + r;
        size_t sb = (size_t)s_src[er] * DD + c0;
        size_t db = (size_t)s_dst[er] * DD + c0;
        float4 dh0 = *(const float4*)(Dh + sb);
        float4 dh1 = *(const float4*)(Dh + sb + 4);
        float4 eh0 = *(const float4*)(Eh + db);
        float4 eh1 = *(const float4*)(Eh + db + 4);
        float2 a0 = upk(acc[r][0]), a1 = upk(acc[r][1]);
        float2 a2 = upk(acc[r][2]), a3 = upk(acc[r][3]);
        float4 v0, v1;
        v0.x = a0.x + dh0.x + eh0.x; v0.y = a0.y + dh0.y + eh0.y;
        v0.z = a1.x + dh0.z + eh0.z; v0.w = a1.y + dh0.w + eh0.w;
        v1.x = a2.x + dh1.x + eh1.x; v1.y = a2.y + dh1.y + eh1.y;
        v1.z = a3.x + dh1.z + eh1.z; v1.w = a3.y + dh1.w + eh1.w;
        size_t ob = (size_t)(ebase + er) * DD + c0;
        *(float4*)(g_enew + ob)     = v0;
        *(float4*)(g_enew + ob + 4) = v1;
        cs[0] += v0.x; cs[1] += v0.y; cs[2] += v0.z; cs[3] += v0.w;
        cs[4] += v1.x; cs[5] += v1.y; cs[6] += v1.z; cs[7] += v1.w;
        cq[0] += v0.x * v0.x; cq[1] += v0.y * v0.y; cq[2] += v0.z * v0.z; cq[3] += v0.w * v0.w;
        cq[4] += v1.x * v1.x; cq[5] += v1.y * v1.y; cq[6] += v1.z * v1.z; cq[7] += v1.w * v1.w;
    }
    if (do_stats) {
#pragma unroll
        for (int j = 0; j < 8; j++) {
            atomicAdd(&s_sum[c0 + j], cs[j]);
            atomicAdd(&s_sq[c0 + j], cq[j]);
        }
        __syncthreads();
        if (t < DD) {
            atomicAdd(&g_esum[t], (double)s_sum[t]);
            atomicAdd(&g_esq[t], (double)s_sq[t]);
        }
    }
}

// ------------------------- aggregation (CSR, sequential enew) -----------------
__global__ __launch_bounds__(256) void k_agg() {
    __shared__ float ssum[DD], ssq[DD];
    int t = threadIdx.x;
    if (t < DD) { ssum[t] = 0.f; ssq[t] = 0.f; }
    __syncthreads();
    int w = t >> 5, ln = t & 31;
    int v = blockIdx.x * 8 + w;      // grid = NN/8 exact
    const float* Ah = g_ABDE;
    const float* Bh = g_ABDE + (size_t)NN * DD;
    float n0 = 0, n1 = 0, n2 = 0, d0 = 0, d1 = 0, d2 = 0;
    int p0 = g_ptr[v], p1 = g_ptr[v + 1];
    for (int p = p0; p < p1; p++) {
        int s = g_srcp[p];
        size_t eb = (size_t)p * DD;
        size_t sb = (size_t)s * DD;
        float x0 = g_enew[eb + ln], x1 = g_enew[eb + ln + 32], x2 = g_enew[eb + ln + 64];
        float s0 = __fdividef(1.f, 1.f + __expf(-x0));
        float s1 = __fdividef(1.f, 1.f + __expf(-x1));
        float s2 = __fdividef(1.f, 1.f + __expf(-x2));
        n0 += s0 * Bh[sb + ln]; n1 += s1 * Bh[sb + ln + 32]; n2 += s2 * Bh[sb + ln + 64];
        d0 += s0; d1 += s1; d2 += s2;
    }
    size_t vb = (size_t)v * DD;
    float h0 = Ah[vb + ln]      + __fdividef(n0, d0 + 1e-6f);
    float h1 = Ah[vb + ln + 32] + __fdividef(n1, d1 + 1e-6f);
    float h2 = Ah[vb + ln + 64] + __fdividef(n2, d2 + 1e-6f);
    g_hnew[vb + ln] = h0; g_hnew[vb + ln + 32] = h1; g_hnew[vb + ln + 64] = h2;
    atomicAdd(&ssum[ln], h0);      atomicAdd(&ssum[ln + 32], h1); atomicAdd(&ssum[ln + 64], h2);
    atomicAdd(&ssq[ln], h0 * h0);  atomicAdd(&ssq[ln + 32], h1 * h1); atomicAdd(&ssq[ln + 64], h2 * h2);
    __syncthreads();
    if (t < DD) {
        atomicAdd(&g_hsum[t], (double)ssum[t]);
        atomicAdd(&g_hsq[t], (double)ssq[t]);
    }
}

// ------------------------- BN finalize ----------------------------------------
__global__ void k_finalize(const float* __restrict__ gamma, const float* __restrict__ beta,
                           double count, int which) {
    int c = threadIdx.x;
    if (c >= DD) return;
    double s, q;
    if (which == 0) { s = g_esum[c]; q = g_esq[c]; g_esum[c] = 0.0; g_esq[c] = 0.0; }
    else            { s = g_hsum[c]; q = g_hsq[c]; g_hsum[c] = 0.0; g_hsq[c] = 0.0; }
    double m = s / count;
    double var = q / count - m * m;
    float sc = gamma[c] * rsqrtf((float)var + 1e-5f);
    float sh = beta[c] - (float)m * sc;
    if (which == 0) { g_escale[c] = sc; g_eshift[c] = sh; }
    else            { g_hscale[c] = sc; g_hshift[c] = sh; }
}

// ------------------------- head: relu(h@W1+b1)@W2+b2, tanh, scale -------------
// Applies the last layer's h update lazily (no writeback needed).
__global__ __launch_bounds__(256) void k_head(const float* __restrict__ W1,
                                              const float* __restrict__ b1,
                                              const float* __restrict__ W2,
                                              const float* __restrict__ b2,
                                              const float* __restrict__ maxa,
                                              float* __restrict__ out) {
    extern __shared__ float dyn[];
    float* W1s = dyn;                 // 96*128
    float* Hs  = W1s + DD * HIDN;     // 32*96
    float* His = Hs + 32 * DD;        // 32*132 (padded)
    float* W2s = His + 32 * 132;      // 128*8
    int t = threadIdx.x;
    for (int i = t; i < DD * HIDN; i += 256) W1s[i] = W1[i];
    for (int i = t; i < HIDN * OUTN; i += 256) W2s[i] = W2[i];
    int row0 = blockIdx.x * 32;
    for (int i = t; i < 32 * 24; i += 256) {
        int r = i / 24, c4 = (i - (i / 24) * 24) * 4;
        int gr = row0 + r;
        float4 v = make_float4(0.f, 0.f, 0.f, 0.f);
        if (gr < NN) {
            size_t idx = (size_t)gr * DD + c4;
            v = *(const float4*)(g_h + idx);
            float4 en = *(const float4*)(g_hnew + idx);
            float4 sc = *(const float4*)(g_hscale + c4);
            float4 sh = *(const float4*)(g_hshift + c4);
            v.x += fmaxf(sc.x * en.x + sh.x, 0.f);
            v.y += fmaxf(sc.y * en.y + sh.y, 0.f);
            v.z += fmaxf(sc.z * en.z + sh.z, 0.f);
            v.w += fmaxf(sc.w * en.w + sh.w, 0.f);
        }
        *(float4*)(Hs + r * DD + c4) = v;
    }
    __syncthreads();
    {
        int ng = t >> 5, hg = t & 31;
        int r0 = ng * 4, c0 = hg * 4;
        ull acc[4][2];
        float4 bv = *(const float4*)(b1 + c0);
        ull b01 = pk2(bv.x, bv.y), b23 = pk2(bv.z, bv.w);
#pragma unroll
        for (int r = 0; r < 4; r++) { acc[r][0] = b01; acc[r][1] = b23; }
#pragma unroll 4
        for (int k = 0; k < DD; k++) {
            ulonglong2 wv = *(const ulonglong2*)(W1s + k * HIDN + c0);
#pragma unroll
            for (int r = 0; r < 4; r++) {
                float x = Hs[(r0 + r) * DD + k];
                ull xx = pk2(x, x);
                acc[r][0] = fma2(xx, wv.x, acc[r][0]);
                acc[r][1] = fma2(xx, wv.y, acc[r][1]);
            }
        }
#pragma unroll
        for (int r = 0; r < 4; r++) {
            float2 a = upk(acc[r][0]), q = upk(acc[r][1]);
            His[(r0 + r) * 132 + c0 + 0] = fmaxf(a.x, 0.f);
            His[(r0 + r) * 132 + c0 + 1] = fmaxf(a.y, 0.f);
            His[(r0 + r) * 132 + c0 + 2] = fmaxf(q.x, 0.f);
            His[(r0 + r) * 132 + c0 + 3] = fmaxf(q.y, 0.f);
        }
    }
    __syncthreads();
    {
        int node = t >> 3, oc = t & 7;
        int gn = row0 + node;
        if (gn < NN) {
            float acc = b2[oc];
#pragma unroll 8
            for (int k = 0; k < HIDN; k++) acc += His[node * 132 + k] * W2s[k * OUTN + oc];
            out[(size_t)gn * OUTN + oc] = maxa[gn] * tanhf(acc);
        }
    }
}

// ------------------------- launch ---------------------------------------------
extern "C" void kernel_launch(void* const* d_in, const int* in_sizes, int n_in,
                              void* d_out, int out_size) {
    const float* h1      = (const float*)d_in[0];
    const float* h2      = (const float*)d_in[1];
    const float* z       = (const float*)d_in[2];
    const float* efeat   = (const float*)d_in[3];
    const float* maxa    = (const float*)d_in[4];
    const float* Wh_emb  = (const float*)d_in[5];
    const float* bh_emb  = (const float*)d_in[6];
    const float* We_emb  = (const float*)d_in[7];
    const float* be_emb  = (const float*)d_in[8];
    const float* WA      = (const float*)d_in[9];
    const float* bA      = (const float*)d_in[10];
    const float* WB      = (const float*)d_in[11];
    const float* bB      = (const float*)d_in[12];
    const float* WC      = (const float*)d_in[13];
    const float* bC      = (const float*)d_in[14];
    const float* WD      = (const float*)d_in[15];
    const float* bD      = (const float*)d_in[16];
    const float* WE      = (const float*)d_in[17];
    const float* bE      = (const float*)d_in[18];
    const float* bn_h_g  = (const float*)d_in[19];
    const float* bn_h_b  = (const float*)d_in[20];
    const float* bn_e_g  = (const float*)d_in[21];
    const float* bn_e_b  = (const float*)d_in[22];
    const float* W1      = (const float*)d_in[23];
    const float* b1      = (const float*)d_in[24];
    const float* W2      = (const float*)d_in[25];
    const float* b2      = (const float*)d_in[26];
    const int*   src     = (const int*)d_in[27];
    const int*   dst     = (const int*)d_in[28];
    float* out = (float*)d_out;

    cudaFuncSetAttribute(k_matABDE, cudaFuncAttributeMaxDynamicSharedMemorySize, 200 * 1024);
    cudaFuncSetAttribute(k_edge,    cudaFuncAttributeMaxDynamicSharedMemorySize, 100 * 1024);
    cudaFuncSetAttribute(k_head,    cudaFuncAttributeMaxDynamicSharedMemorySize, 96 * 1024);

    const int smem_abde = (DD * 384 + 64 * DD + 384) * 4;                       // ~173 KB
    const int smem_edge = (DD * DD + 128 * DD) * 4;                             // 86 KB
    const int smem_head = (DD * HIDN + 32 * DD + 32 * 132 + HIDN * OUTN) * 4;   // 82432

    k_zero<<<(NN + 255) / 256, 256>>>();
    k_embed_h<<<(NN * DD + 255) / 256, 256>>>(h1, h2, z, Wh_emb, bh_emb);

    k_count<<<EE / 256, 256>>>(dst);
    k_scan1<<<NBS, 256>>>();
    k_scan2<<<1, 256>>>();
    k_scan3<<<NBS, 256>>>();
    k_fill<<<EE / 256, 256>>>(dst);
    k_sortseg<<<(NN + 127) / 128, 128>>>();
    k_embed_e_perm<<<EE / 8, 256>>>(efeat, src, dst, We_emb, be_emb);

    const int ablk = (NN + 63) / 64;   // 782
    const int eblk = EE / 128;         // 6250
    const int hblk = (NN + 31) / 32;   // 1563

    for (int l = 0; l < 4; l++) {
        k_matABDE<<<ablk, 384, smem_abde>>>(WA + l * DD * DD, WB + l * DD * DD,
                                            WD + l * DD * DD, WE + l * DD * DD,
                                            bA + l * DD, bB + l * DD,
                                            bD + l * DD, bE + l * DD,
                                            l >= 1 ? 1 : 0);

        int apply = (l >= 1) ? 1 : 0;
        int write_e = (l >= 1 && l < 3) ? 1 : 0;
        int do_stats = (l < 3) ? 1 : 0;
        k_edge<<<eblk, 192, smem_edge>>>(WC + l * DD * DD, bC + l * DD,
                                         apply, write_e, do_stats);
        if (l < 3)
            k_finalize<<<1, DD>>>(bn_e_g + l * DD, bn_e_b + l * DD, (double)EE, 0);

        k_agg<<<NN / 8, 256>>>();
        k_finalize<<<1, DD>>>(bn_h_g + l * DD, bn_h_b + l * DD, (double)NN, 1);
    }

    k_head<<<hblk, 256, smem_head>>>(W1, b1, W2, b2, maxa, out);
}

// round 4
// speedup vs baseline: 1.1654x; 1.1654x over previous
#include <cuda_runtime.h>
#include <math.h>

#define NN 50000
#define EE 800000
#define DD 96
#define HIDN 128
#define OUTN 8
#define NBS 196   // scan blocks = ceil(NN/256)
#define ESTR 108  // padded smem row stride (floats) for conflict-free mma feeds

typedef unsigned long long ull;

// ------------------------- device scratch (no allocs allowed) ----------------
__device__ float g_h[(size_t)NN * DD];
__device__ float g_hnew[(size_t)NN * DD];
__device__ float g_ABDE[(size_t)4 * NN * DD];   // A,B,D,E
__device__ float g_e[(size_t)EE * DD];          // permuted (CSR dst order)
__device__ float g_enew[(size_t)EE * DD];       // permuted
__device__ int   g_cnt[NN];
__device__ int   g_ptr[NN + 1];
__device__ int   g_woff[NN];
__device__ int   g_eid[EE];
__device__ int   g_srcp[EE];
__device__ int   g_dstp[EE];
__device__ int   g_bsum[256];
__device__ int   g_boff[256];
__device__ double g_esum[DD], g_esq[DD], g_hsum[DD], g_hsq[DD];
__device__ float g_escale[DD], g_eshift[DD], g_hscale[DD], g_hshift[DD];

// ------------------------- packed f32x2 helpers ------------------------------
__device__ __forceinline__ ull pk2(float lo, float hi) {
    ull r; asm("mov.b64 %0,{%1,%2};" : "=l"(r) : "f"(lo), "f"(hi)); return r;
}
__device__ __forceinline__ ull fma2(ull a, ull b, ull c) {
    ull d; asm("fma.rn.f32x2 %0,%1,%2,%3;" : "=l"(d) : "l"(a), "l"(b), "l"(c)); return d;
}
__device__ __forceinline__ float2 upk(ull v) {
    float2 f; asm("mov.b64 {%0,%1},%2;" : "=f"(f.x), "=f"(f.y) : "l"(v)); return f;
}
__device__ __forceinline__ float tf32r(float x) {
    unsigned u; asm("cvt.rna.tf32.f32 %0,%1;" : "=r"(u) : "f"(x));
    return __uint_as_float(u);
}
#define MMA_TF32(d, a, b0_, b1_) \
    asm volatile("mma.sync.aligned.m16n8k8.row.col.f32.tf32.tf32.f32 " \
        "{%0,%1,%2,%3},{%4,%5,%6,%7},{%8,%9},{%0,%1,%2,%3};" \
        : "+f"(d[0]), "+f"(d[1]), "+f"(d[2]), "+f"(d[3]) \
        : "r"(a[0]), "r"(a[1]), "r"(a[2]), "r"(a[3]), "r"(b0_), "r"(b1_))

// ------------------------- setup kernels -------------------------------------
__global__ void k_zero() {
    int i = blockIdx.x * blockDim.x + threadIdx.x;
    if (i < NN) g_cnt[i] = 0;
    if (i < DD) { g_esum[i] = 0.0; g_esq[i] = 0.0; g_hsum[i] = 0.0; g_hsq[i] = 0.0; }
}

__global__ void k_embed_h(const float* __restrict__ h1, const float* __restrict__ h2,
                          const float* __restrict__ z,
                          const float* __restrict__ W, const float* __restrict__ b) {
    __shared__ float Ws[26 * DD];
    int t = threadIdx.x;
    for (int i = t; i < 26 * DD; i += blockDim.x) Ws[i] = W[i];
    __syncthreads();
    int idx = blockIdx.x * blockDim.x + t;
    if (idx >= NN * DD) return;
    int r = idx / DD, c = idx - (idx / DD) * DD;
    float acc = b[c];
#pragma unroll
    for (int k = 0; k < 6; k++)  acc += h1[r * 6 + k]  * Ws[k * DD + c];
#pragma unroll
    for (int k = 0; k < 4; k++)  acc += h2[r * 4 + k]  * Ws[(6 + k) * DD + c];
#pragma unroll
    for (int k = 0; k < 16; k++) acc += z[r * 16 + k]  * Ws[(10 + k) * DD + c];
    g_h[idx] = acc;
}

// ------------------------- CSR build (deterministic, parallel scan) -----------
__global__ void k_count(const int* __restrict__ dst) {
    int i = blockIdx.x * blockDim.x + threadIdx.x;
    if (i < EE) atomicAdd(&g_cnt[dst[i]], 1);
}

__global__ void k_scan1() {
    __shared__ int sh[256];
    int t = threadIdx.x, b = blockIdx.x;
    int j = b * 256 + t;
    int v = (j < NN) ? g_cnt[j] : 0;
    sh[t] = v; __syncthreads();
    for (int off = 1; off < 256; off <<= 1) {
        int u = (t >= off) ? sh[t - off] : 0;
        __syncthreads();
        sh[t] += u;
        __syncthreads();
    }
    if (j < NN) g_ptr[j] = sh[t] - v;
    if (t == 255) g_bsum[b] = sh[t];
}

__global__ void k_scan2() {
    __shared__ int sh[256];
    int t = threadIdx.x;
    int v = (t < NBS) ? g_bsum[t] : 0;
    sh[t] = v; __syncthreads();
    for (int off = 1; off < 256; off <<= 1) {
        int u = (t >= off) ? sh[t - off] : 0;
        __syncthreads();
        sh[t] += u;
        __syncthreads();
    }
    g_boff[t] = sh[t] - v;
}

__global__ void k_scan3() {
    int j = blockIdx.x * blockDim.x + threadIdx.x;
    if (j < NN) {
        int p = g_ptr[j] + g_boff[j >> 8];
        g_ptr[j] = p; g_woff[j] = p;
    }
    if (j == 0) g_ptr[NN] = EE;
}

__global__ void k_fill(const int* __restrict__ dst) {
    int i = blockIdx.x * blockDim.x + threadIdx.x;
    if (i < EE) {
        int pos = atomicAdd(&g_woff[dst[i]], 1);
        g_eid[pos] = i;
    }
}

__global__ void k_sortseg() {
    int v = blockIdx.x * blockDim.x + threadIdx.x;
    if (v >= NN) return;
    int lo = g_ptr[v], hi = g_ptr[v + 1];
    for (int i = lo + 1; i < hi; i++) {
        int key = g_eid[i]; int j = i - 1;
        while (j >= lo && g_eid[j] > key) { g_eid[j + 1] = g_eid[j]; j--; }
        g_eid[j + 1] = key;
    }
}

// Embed edges directly into permuted (CSR) order; also build permuted src/dst.
__global__ __launch_bounds__(256) void k_embed_e_perm(const float* __restrict__ ef,
                                                      const int* __restrict__ src,
                                                      const int* __restrict__ dst,
                                                      const float* __restrict__ W,
                                                      const float* __restrict__ b) {
    __shared__ float Ws[4 * DD], bs[DD];
    int t = threadIdx.x;
    for (int i = t; i < 4 * DD; i += 256) Ws[i] = W[i];
    if (t < DD) bs[t] = b[t];
    __syncthreads();
    int w = t >> 5, ln = t & 31;
    int p = blockIdx.x * 8 + w;        // grid = EE/8 exact
    int ei = g_eid[p];
    float4 f = *(const float4*)(ef + (size_t)ei * 4);
    if (ln == 0) g_srcp[p] = src[ei];
    if (ln == 1) g_dstp[p] = dst[ei];
#pragma unroll
    for (int j = 0; j < 3; j++) {
        int c = ln + j * 32;
        g_e[(size_t)p * DD + c] = bs[c] + f.x * Ws[c] + f.y * Ws[DD + c]
                                 + f.z * Ws[2 * DD + c] + f.w * Ws[3 * DD + c];
    }
}

// ------------------------- fused node GEMM: [A|B|D|E] = h @ Wcat + bcat -------
// (Round-2 proven shape: 32 rows/block, 8x4 per-thread tile, 384 threads.)
// Lazily applies h += relu(bn(hnew)) from the previous layer (writes g_h).
__global__ __launch_bounds__(384) void k_matABDE(const float* __restrict__ WA_,
                                                 const float* __restrict__ WB_,
                                                 const float* __restrict__ WD_,
                                                 const float* __restrict__ WE_,
                                                 const float* __restrict__ bA_,
                                                 const float* __restrict__ bB_,
                                                 const float* __restrict__ bD_,
                                                 const float* __restrict__ bE_,
                                                 int apply) {
    extern __shared__ float dyn[];
    float* Ws = dyn;                    // [96][384] concat
    float* Xs = dyn + DD * 384;         // [32][96]
    float* Bs = Xs + 32 * DD;           // [384]
    int t = threadIdx.x;
    const float* wsrc[4] = {WA_, WB_, WD_, WE_};
    const float* bsrc[4] = {bA_, bB_, bD_, bE_};
#pragma unroll
    for (int m = 0; m < 4; m++) {
        for (int i = t; i < DD * DD; i += 384) {
            int k = i / DD, c = i - k * DD;
            Ws[k * 384 + m * DD + c] = wsrc[m][i];
        }
        if (t < DD) Bs[m * DD + t] = bsrc[m][t];
    }
    int row0 = blockIdx.x * 32;
    for (int i = t; i < 32 * 24; i += 384) {
        int r = i / 24, c4 = (i - (i / 24) * 24) * 4;
        int gr = row0 + r;
        float4 v = make_float4(0.f, 0.f, 0.f, 0.f);
        if (gr < NN) {
            size_t idx = (size_t)gr * DD + c4;
            v = *(const float4*)(g_h + idx);
            if (apply) {
                float4 en = *(const float4*)(g_hnew + idx);
                float4 sc = *(const float4*)(g_hscale + c4);
                float4 sh = *(const float4*)(g_hshift + c4);
                v.x += fmaxf(sc.x * en.x + sh.x, 0.f);
                v.y += fmaxf(sc.y * en.y + sh.y, 0.f);
                v.z += fmaxf(sc.z * en.z + sh.z, 0.f);
                v.w += fmaxf(sc.w * en.w + sh.w, 0.f);
                *(float4*)(g_h + idx) = v;
            }
        }
        *(float4*)(Xs + r * DD + c4) = v;
    }
    __syncthreads();
    int cg = t % 96, rg = t / 96;
    int c0 = cg * 4, r0 = rg * 8;
    ull acc[8][2];
    ull b01 = pk2(Bs[c0], Bs[c0 + 1]), b23 = pk2(Bs[c0 + 2], Bs[c0 + 3]);
#pragma unroll
    for (int r = 0; r < 8; r++) { acc[r][0] = b01; acc[r][1] = b23; }
#pragma unroll 6
    for (int k = 0; k < DD; k += 2) {
        ulonglong2 w0 = *(const ulonglong2*)(Ws + k * 384 + c0);
        ulonglong2 w1 = *(const ulonglong2*)(Ws + (k + 1) * 384 + c0);
#pragma unroll
        for (int r = 0; r < 8; r++) {
            float2 x = *(const float2*)(Xs + (r0 + r) * DD + k);
            ull x0 = pk2(x.x, x.x), x1 = pk2(x.y, x.y);
            acc[r][0] = fma2(x0, w0.x, acc[r][0]);
            acc[r][1] = fma2(x0, w0.y, acc[r][1]);
            acc[r][0] = fma2(x1, w1.x, acc[r][0]);
            acc[r][1] = fma2(x1, w1.y, acc[r][1]);
        }
    }
    int m = c0 / DD, cc = c0 - m * DD;
    float* outp = g_ABDE + (size_t)m * NN * DD;
#pragma unroll
    for (int r = 0; r < 8; r++) {
        int gr = row0 + r0 + r;
        if (gr < NN) {
            float2 a = upk(acc[r][0]), q = upk(acc[r][1]);
            *(float4*)(outp + (size_t)gr * DD + cc) = make_float4(a.x, a.y, q.x, q.y);
        }
    }
}

// ------------------------- edge kernel: tf32 tensor-core GEMM -----------------
// 128 edges/block, 8 warps; warp w owns 32 edges x 48 cols (2 m16 x 6 n8 tiles).
// e_new = tf32mma(e, WC) + bC + Dh[src] + Eh[dst]; lazy BN apply on staging;
// BN-e stats via shfl-reduced smem atomics.
__global__ __launch_bounds__(256) void k_edge(const float* __restrict__ W,
                                              const float* __restrict__ b,
                                              int apply, int write_e, int do_stats) {
    extern __shared__ float dyn[];
    float* Ws = dyn;                  // [96][ESTR]
    float* Es = dyn + DD * ESTR;      // [128][ESTR]
    __shared__ float s_sum[DD], s_sq[DD], bsh[DD];
    __shared__ int s_src[128], s_dst[128];
    int t = threadIdx.x;
    int lane = t & 31, w = t >> 5;
    if (t < DD) { s_sum[t] = 0.f; s_sq[t] = 0.f; bsh[t] = b[t]; }
    // stage W, rounded to tf32
    for (int i = t; i < DD * 24; i += 256) {
        int k = i / 24, c4 = (i - (i / 24) * 24) * 4;
        float4 v = *(const float4*)(W + k * DD + c4);
        v.x = tf32r(v.x); v.y = tf32r(v.y); v.z = tf32r(v.z); v.w = tf32r(v.w);
        *(float4*)(Ws + k * ESTR + c4) = v;
    }
    int ebase = blockIdx.x * 128;   // EE % 128 == 0
    if (t < 128) { s_src[t] = g_srcp[ebase + t]; s_dst[t] = g_dstp[ebase + t]; }
    // stage e with lazy BN apply; keep f32 in gmem, tf32-rounded copy in smem
    for (int i = t; i < 128 * 24; i += 256) {
        int r = i / 24, c4 = (i - (i / 24) * 24) * 4;
        size_t idx = (size_t)(ebase + r) * DD + c4;
        float4 v = *(const float4*)(g_e + idx);
        if (apply) {
            float4 en = *(const float4*)(g_enew + idx);
            float4 sc = *(const float4*)(g_escale + c4);
            float4 sh = *(const float4*)(g_eshift + c4);
            v.x += fmaxf(sc.x * en.x + sh.x, 0.f);
            v.y += fmaxf(sc.y * en.y + sh.y, 0.f);
            v.z += fmaxf(sc.z * en.z + sh.z, 0.f);
            v.w += fmaxf(sc.w * en.w + sh.w, 0.f);
            if (write_e) *(float4*)(g_e + idx) = v;
        }
        v.x = tf32r(v.x); v.y = tf32r(v.y); v.z = tf32r(v.z); v.w = tf32r(v.w);
        *(float4*)(Es + r * ESTR + c4) = v;
    }
    __syncthreads();

    int mg = w >> 1, ng = w & 1;
    int m0 = mg * 32, n0 = ng * 48;
    int g = lane >> 2, c4 = lane & 3;
    float acc[2][6][4];
#pragma unroll
    for (int i = 0; i < 2; i++)
#pragma unroll
        for (int j = 0; j < 6; j++)
#pragma unroll
            for (int q = 0; q < 4; q++) acc[i][j][q] = 0.f;

#pragma unroll
    for (int k0 = 0; k0 < DD; k0 += 8) {
        unsigned a[2][4];
#pragma unroll
        for (int i = 0; i < 2; i++) {
            int rr = (m0 + i * 16 + g) * ESTR;
            a[i][0] = __float_as_uint(Es[rr + k0 + c4]);
            a[i][1] = __float_as_uint(Es[rr + 8 * ESTR + k0 + c4]);
            a[i][2] = __float_as_uint(Es[rr + k0 + 4 + c4]);
            a[i][3] = __float_as_uint(Es[rr + 8 * ESTR + k0 + 4 + c4]);
        }
#pragma unroll
        for (int j = 0; j < 6; j++) {
            int col = n0 + 8 * j + g;
            unsigned b0 = __float_as_uint(Ws[(k0 + c4) * ESTR + col]);
            unsigned b1 = __float_as_uint(Ws[(k0 + 4 + c4) * ESTR + col]);
            MMA_TF32(acc[0][j], a[0], b0, b1);
            MMA_TF32(acc[1][j], a[1], b0, b1);
        }
    }

    // epilogue: add bias + gathers, write enew, accumulate stats
    const float* Dh = g_ABDE + (size_t)2 * NN * DD;
    const float* Eh = g_ABDE + (size_t)3 * NN * DD;
    float cs[6][2], cq[6][2];
#pragma unroll
    for (int j = 0; j < 6; j++) { cs[j][0] = cs[j][1] = 0.f; cq[j][0] = cq[j][1] = 0.f; }
#pragma unroll
    for (int i = 0; i < 2; i++) {
#pragma unroll
        for (int half = 0; half < 2; half++) {
            int rl = m0 + i * 16 + half * 8 + g;
            size_t sb = (size_t)s_src[rl] * DD;
            size_t db = (size_t)s_dst[rl] * DD;
            size_t ob = (size_t)(ebase + rl) * DD;
#pragma unroll
            for (int j = 0; j < 6; j++) {
                int col = n0 + 8 * j + 2 * c4;
                float2 dh = *(const float2*)(Dh + sb + col);
                float2 eh = *(const float2*)(Eh + db + col);
                float v0 = acc[i][j][half * 2 + 0] + bsh[col]     + dh.x + eh.x;
                float v1 = acc[i][j][half * 2 + 1] + bsh[col + 1] + dh.y + eh.y;
                float2 vv = make_float2(v0, v1);
                *(float2*)(g_enew + ob + col) = vv;
                cs[j][0] += v0; cs[j][1] += v1;
                cq[j][0] += v0 * v0; cq[j][1] += v1 * v1;
            }
        }
    }
    if (do_stats) {
#pragma unroll
        for (int off = 16; off >= 4; off >>= 1) {
#pragma unroll
            for (int j = 0; j < 6; j++) {
#pragma unroll
                for (int p = 0; p < 2; p++) {
                    cs[j][p] += __shfl_down_sync(0xffffffffu, cs[j][p], off);
                    cq[j][p] += __shfl_down_sync(0xffffffffu, cq[j][p], off);
                }
            }
        }
        if (lane < 4) {
#pragma unroll
            for (int j = 0; j < 6; j++) {
#pragma unroll
                for (int p = 0; p < 2; p++) {
                    int col = n0 + 8 * j + 2 * lane + p;
                    atomicAdd(&s_sum[col], cs[j][p]);
                    atomicAdd(&s_sq[col], cq[j][p]);
                }
            }
        }
        __syncthreads();
        if (t < DD) {
            atomicAdd(&g_esum[t], (double)s_sum[t]);
            atomicAdd(&g_esq[t], (double)s_sq[t]);
        }
    }
}

// ------------------------- aggregation (CSR, sequential enew) -----------------
__global__ __launch_bounds__(256) void k_agg() {
    __shared__ float ssum[DD], ssq[DD];
    int t = threadIdx.x;
    if (t < DD) { ssum[t] = 0.f; ssq[t] = 0.f; }
    __syncthreads();
    int w = t >> 5, ln = t & 31;
    int v = blockIdx.x * 8 + w;      // grid = NN/8 exact
    const float* Ah = g_ABDE;
    const float* Bh = g_ABDE + (size_t)NN * DD;
    float n0 = 0, n1 = 0, n2 = 0, d0 = 0, d1 = 0, d2 = 0;
    int p0 = g_ptr[v], p1 = g_ptr[v + 1];
    for (int p = p0; p < p1; p++) {
        int s = g_srcp[p];
        size_t eb = (size_t)p * DD;
        size_t sb = (size_t)s * DD;
        float x0 = g_enew[eb + ln], x1 = g_enew[eb + ln + 32], x2 = g_enew[eb + ln + 64];
        float s0 = __fdividef(1.f, 1.f + __expf(-x0));
        float s1 = __fdividef(1.f, 1.f + __expf(-x1));
        float s2 = __fdividef(1.f, 1.f + __expf(-x2));
        n0 += s0 * Bh[sb + ln]; n1 += s1 * Bh[sb + ln + 32]; n2 += s2 * Bh[sb + ln + 64];
        d0 += s0; d1 += s1; d2 += s2;
    }
    size_t vb = (size_t)v * DD;
    float h0 = Ah[vb + ln]      + __fdividef(n0, d0 + 1e-6f);
    float h1 = Ah[vb + ln + 32] + __fdividef(n1, d1 + 1e-6f);
    float h2 = Ah[vb + ln + 64] + __fdividef(n2, d2 + 1e-6f);
    g_hnew[vb + ln] = h0; g_hnew[vb + ln + 32] = h1; g_hnew[vb + ln + 64] = h2;
    atomicAdd(&ssum[ln], h0);      atomicAdd(&ssum[ln + 32], h1); atomicAdd(&ssum[ln + 64], h2);
    atomicAdd(&ssq[ln], h0 * h0);  atomicAdd(&ssq[ln + 32], h1 * h1); atomicAdd(&ssq[ln + 64], h2 * h2);
    __syncthreads();
    if (t < DD) {
        atomicAdd(&g_hsum[t], (double)ssum[t]);
        atomicAdd(&g_hsq[t], (double)ssq[t]);
    }
}

// ------------------------- BN finalize ----------------------------------------
__global__ void k_finalize(const float* __restrict__ gamma, const float* __restrict__ beta,
                           double count, int which) {
    int c = threadIdx.x;
    if (c >= DD) return;
    double s, q;
    if (which == 0) { s = g_esum[c]; q = g_esq[c]; g_esum[c] = 0.0; g_esq[c] = 0.0; }
    else            { s = g_hsum[c]; q = g_hsq[c]; g_hsum[c] = 0.0; g_hsq[c] = 0.0; }
    double m = s / count;
    double var = q / count - m * m;
    float sc = gamma[c] * rsqrtf((float)var + 1e-5f);
    float sh = beta[c] - (float)m * sc;
    if (which == 0) { g_escale[c] = sc; g_eshift[c] = sh; }
    else            { g_hscale[c] = sc; g_hshift[c] = sh; }
}

// ------------------------- head: relu(h@W1+b1)@W2+b2, tanh, scale -------------
__global__ __launch_bounds__(256) void k_head(const float* __restrict__ W1,
                                              const float* __restrict__ b1,
                                              const float* __restrict__ W2,
                                              const float* __restrict__ b2,
                                              const float* __restrict__ maxa,
                                              float* __restrict__ out) {
    extern __shared__ float dyn[];
    float* W1s = dyn;                 // 96*128
    float* Hs  = W1s + DD * HIDN;     // 32*96
    float* His = Hs + 32 * DD;        // 32*132 (padded)
    float* W2s = His + 32 * 132;      // 128*8
    int t = threadIdx.x;
    for (int i = t; i < DD * HIDN; i += 256) W1s[i] = W1[i];
    for (int i = t; i < HIDN * OUTN; i += 256) W2s[i] = W2[i];
    int row0 = blockIdx.x * 32;
    for (int i = t; i < 32 * 24; i += 256) {
        int r = i / 24, c4 = (i - (i / 24) * 24) * 4;
        int gr = row0 + r;
        float4 v = make_float4(0.f, 0.f, 0.f, 0.f);
        if (gr < NN) {
            size_t idx = (size_t)gr * DD + c4;
            v = *(const float4*)(g_h + idx);
            float4 en = *(const float4*)(g_hnew + idx);
            float4 sc = *(const float4*)(g_hscale + c4);
            float4 sh = *(const float4*)(g_hshift + c4);
            v.x += fmaxf(sc.x * en.x + sh.x, 0.f);
            v.y += fmaxf(sc.y * en.y + sh.y, 0.f);
            v.z += fmaxf(sc.z * en.z + sh.z, 0.f);
            v.w += fmaxf(sc.w * en.w + sh.w, 0.f);
        }
        *(float4*)(Hs + r * DD + c4) = v;
    }
    __syncthreads();
    {
        int ng = t >> 5, hg = t & 31;
        int r0 = ng * 4, c0 = hg * 4;
        ull acc[4][2];
        float4 bv = *(const float4*)(b1 + c0);
        ull b01 = pk2(bv.x, bv.y), b23 = pk2(bv.z, bv.w);
#pragma unroll
        for (int r = 0; r < 4; r++) { acc[r][0] = b01; acc[r][1] = b23; }
#pragma unroll 4
        for (int k = 0; k < DD; k++) {
            ulonglong2 wv = *(const ulonglong2*)(W1s + k * HIDN + c0);
#pragma unroll
            for (int r = 0; r < 4; r++) {
                float x = Hs[(r0 + r) * DD + k];
                ull xx = pk2(x, x);
                acc[r][0] = fma2(xx, wv.x, acc[r][0]);
                acc[r][1] = fma2(xx, wv.y, acc[r][1]);
            }
        }
#pragma unroll
        for (int r = 0; r < 4; r++) {
            float2 a = upk(acc[r][0]), q = upk(acc[r][1]);
            His[(r0 + r) * 132 + c0 + 0] = fmaxf(a.x, 0.f);
            His[(r0 + r) * 132 + c0 + 1] = fmaxf(a.y, 0.f);
            His[(r0 + r) * 132 + c0 + 2] = fmaxf(q.x, 0.f);
            His[(r0 + r) * 132 + c0 + 3] = fmaxf(q.y, 0.f);
        }
    }
    __syncthreads();
    {
        int node = t >> 3, oc = t & 7;
        int gn = row0 + node;
        if (gn < NN) {
            float acc = b2[oc];
#pragma unroll 8
            for (int k = 0; k < HIDN; k++) acc += His[node * 132 + k] * W2s[k * OUTN + oc];
            out[(size_t)gn * OUTN + oc] = maxa[gn] * tanhf(acc);
        }
    }
}

// ------------------------- launch ---------------------------------------------
extern "C" void kernel_launch(void* const* d_in, const int* in_sizes, int n_in,
                              void* d_out, int out_size) {
    const float* h1      = (const float*)d_in[0];
    const float* h2      = (const float*)d_in[1];
    const float* z       = (const float*)d_in[2];
    const float* efeat   = (const float*)d_in[3];
    const float* maxa    = (const float*)d_in[4];
    const float* Wh_emb  = (const float*)d_in[5];
    const float* bh_emb  = (const float*)d_in[6];
    const float* We_emb  = (const float*)d_in[7];
    const float* be_emb  = (const float*)d_in[8];
    const float* WA      = (const float*)d_in[9];
    const float* bA      = (const float*)d_in[10];
    const float* WB      = (const float*)d_in[11];
    const float* bB      = (const float*)d_in[12];
    const float* WC      = (const float*)d_in[13];
    const float* bC      = (const float*)d_in[14];
    const float* WD      = (const float*)d_in[15];
    const float* bD      = (const float*)d_in[16];
    const float* WE      = (const float*)d_in[17];
    const float* bE      = (const float*)d_in[18];
    const float* bn_h_g  = (const float*)d_in[19];
    const float* bn_h_b  = (const float*)d_in[20];
    const float* bn_e_g  = (const float*)d_in[21];
    const float* bn_e_b  = (const float*)d_in[22];
    const float* W1      = (const float*)d_in[23];
    const float* b1      = (const float*)d_in[24];
    const float* W2      = (const float*)d_in[25];
    const float* b2      = (const float*)d_in[26];
    const int*   src     = (const int*)d_in[27];
    const int*   dst     = (const int*)d_in[28];
    float* out = (float*)d_out;

    cudaFuncSetAttribute(k_matABDE, cudaFuncAttributeMaxDynamicSharedMemorySize, 192 * 1024);
    cudaFuncSetAttribute(k_edge,    cudaFuncAttributeMaxDynamicSharedMemorySize, 100 * 1024);
    cudaFuncSetAttribute(k_head,    cudaFuncAttributeMaxDynamicSharedMemorySize, 96 * 1024);

    const int smem_abde = (DD * 384 + 32 * DD + 384) * 4;                       // 161280
    const int smem_edge = (DD + 128) * ESTR * 4;                                // 96768
    const int smem_head = (DD * HIDN + 32 * DD + 32 * 132 + HIDN * OUTN) * 4;   // 82432

    k_zero<<<(NN + 255) / 256, 256>>>();
    k_embed_h<<<(NN * DD + 255) / 256, 256>>>(h1, h2, z, Wh_emb, bh_emb);

    k_count<<<EE / 256, 256>>>(dst);
    k_scan1<<<NBS, 256>>>();
    k_scan2<<<1, 256>>>();
    k_scan3<<<NBS, 256>>>();
    k_fill<<<EE / 256, 256>>>(dst);
    k_sortseg<<<(NN + 127) / 128, 128>>>();
    k_embed_e_perm<<<EE / 8, 256>>>(efeat, src, dst, We_emb, be_emb);

    const int ablk = (NN + 31) / 32;   // 1563
    const int eblk = EE / 128;         // 6250

    for (int l = 0; l < 4; l++) {
        k_matABDE<<<ablk, 384, smem_abde>>>(WA + l * DD * DD, WB + l * DD * DD,
                                            WD + l * DD * DD, WE + l * DD * DD,
                                            bA + l * DD, bB + l * DD,
                                            bD + l * DD, bE + l * DD,
                                            l >= 1 ? 1 : 0);

        int apply = (l >= 1) ? 1 : 0;
        int write_e = (l >= 1 && l < 3) ? 1 : 0;
        int do_stats = (l < 3) ? 1 : 0;
        k_edge<<<eblk, 256, smem_edge>>>(WC + l * DD * DD, bC + l * DD,
                                         apply, write_e, do_stats);
        if (l < 3)
            k_finalize<<<1, DD>>>(bn_e_g + l * DD, bn_e_b + l * DD, (double)EE, 0);

        k_agg<<<NN / 8, 256>>>();
        k_finalize<<<1, DD>>>(bn_h_g + l * DD, bn_h_b + l * DD, (double)NN, 1);
    }

    k_head<<<ablk, 256, smem_head>>>(W1, b1, W2, b2, maxa, out);
}